// round 14
// baseline (speedup 1.0000x reference)
#include <cuda_runtime.h>
#include <cuda_fp16.h>
#include <math.h>

#define NN 10000
#define NPAD 10112          // 79 * 128
#define EE 100000
#define E2 110000
#define HMAX 4
#define CC 200
#define KA 832              // A col stride; layer0 uses cols 0..255
#define WSZ (832 * 896)     // per-layer converted W size

// ---------------- scratch (device globals; no allocs allowed) ----------------
__device__ __half g_Ah[NPAD * KA];        // fp16 activations
__device__ __half g_Wh[5 * WSZ];          // fp16 weights, [layer][Kp][Np]
__device__ __half g_h[NPAD * 896];        // GEMM output h (fp16, padded stride)
__device__ float g_asrc[NN * HMAX];
__device__ float g_adst[NN * HMAX];
__device__ float g_alphaCSR[E2 * HMAX];
__device__ int   g_srcCSR[E2];
__device__ int   g_eidx[E2];
__device__ int   g_srcv[E2];
__device__ int   g_dstv[E2];
__device__ int   g_deg[NN];
__device__ int   g_off[NN + 1];
__device__ int   g_pos[NN];

// ---------------- CSR construction ----------------
__global__ void k_zero_deg() {
    int i = blockIdx.x * blockDim.x + threadIdx.x;
    if (i < NN) g_deg[i] = 0;
}

__global__ void k_build_edges(const int* __restrict__ ei) {
    int e = blockIdx.x * blockDim.x + threadIdx.x;
    if (e >= E2) return;
    int s, d;
    if (e < EE) { s = ei[e]; d = ei[EE + e]; }
    else        { s = d = e - EE; }
    g_srcv[e] = s;
    g_dstv[e] = d;
    atomicAdd(&g_deg[d], 1);
}

__global__ void k_scan() {
    __shared__ int ssum[1024];
    const int CH = (NN + 1023) / 1024;
    int t = threadIdx.x;
    int start = t * CH;
    int local = 0;
    for (int i = 0; i < CH; i++) {
        int idx = start + i;
        if (idx < NN) local += g_deg[idx];
    }
    ssum[t] = local;
    __syncthreads();
    for (int d = 1; d < 1024; d <<= 1) {
        int v = (t >= d) ? ssum[t - d] : 0;
        __syncthreads();
        ssum[t] += v;
        __syncthreads();
    }
    int run = (t == 0) ? 0 : ssum[t - 1];
    for (int i = 0; i < CH; i++) {
        int idx = start + i;
        if (idx < NN) {
            g_off[idx] = run;
            g_pos[idx] = run;
            run += g_deg[idx];
        }
    }
    if (t == 1023) g_off[NN] = ssum[1023];
}

__global__ void k_scatter() {
    int e = blockIdx.x * blockDim.x + threadIdx.x;
    if (e >= E2) return;
    int p = atomicAdd(&g_pos[g_dstv[e]], 1);
    g_eidx[p] = e;
    g_srcCSR[p] = g_srcv[e];
}

// ---------------- conversions ----------------
__global__ void k_init_A(const float* __restrict__ X) {
    int idx = blockIdx.x * blockDim.x + threadIdx.x;
    if (idx >= NPAD * KA) return;
    int r = idx / KA, c = idx % KA;
    float v = (r < NN && c < 200) ? X[r * 200 + c] : 0.f;
    g_Ah[idx] = __float2half(v);
}

__global__ void k_convert_W_all(const float* W0, const float* W1, const float* W2,
                                const float* W3, const float* W4) {
    int idx = blockIdx.x * blockDim.x + threadIdx.x;
    if (idx >= 5 * WSZ) return;
    int layer = idx / WSZ;
    int q = idx % WSZ;
    int Np = (layer == 4) ? 256 : 896;
    int Nc = (layer == 4) ? 200 : 800;
    int K  = (layer == 0) ? 200 : 800;
    if (q >= 832 * Np) return;
    int r = q / Np, c = q % Np;
    const float* W = (layer == 0) ? W0 : (layer == 1) ? W1 : (layer == 2) ? W2
                     : (layer == 3) ? W3 : W4;
    float v = (r < K && c < Nc) ? W[r * Nc + c] : 0.f;
    g_Wh[(size_t)layer * WSZ + q] = __float2half(v);
}

// ---------------- fp16 mma.sync GEMM, ks-pipelined fragments ---------------
#define BK 64
#define STAGE_ELEMS 16384
#define SA_OFF 0
#define SB_OFF 8192

__device__ __forceinline__ unsigned sm_u32(const void* p) {
    return (unsigned)__cvta_generic_to_shared(p);
}

#define CP16(dst, src) \
    asm volatile("cp.async.cg.shared.global [%0], [%1], 16;" :: "r"(dst), "l"(src))
#define LDMX4(r, addr) \
    asm volatile("ldmatrix.sync.aligned.m8n8.x4.shared.b16 {%0,%1,%2,%3}, [%4];" \
        : "=r"((r)[0]), "=r"((r)[1]), "=r"((r)[2]), "=r"((r)[3]) : "r"(addr))
#define LDMX4T(r, addr) \
    asm volatile("ldmatrix.sync.aligned.m8n8.x4.trans.shared.b16 {%0,%1,%2,%3}, [%4];" \
        : "=r"((r)[0]), "=r"((r)[1]), "=r"((r)[2]), "=r"((r)[3]) : "r"(addr))
#define MMAF16(d, a, b) \
    asm volatile("mma.sync.aligned.m16n8k16.row.col.f32.f16.f16.f32 " \
        "{%0,%1,%2,%3}, {%4,%5,%6,%7}, {%8,%9}, {%0,%1,%2,%3};" \
        : "+f"((d)[0]), "+f"((d)[1]), "+f"((d)[2]), "+f"((d)[3]) \
        : "r"((a)[0]), "r"((a)[1]), "r"((a)[2]), "r"((a)[3]), "r"((b)[0]), "r"((b)[1]))

__global__ __launch_bounds__(256, 2) void k_gemm_mma(
    const __half* __restrict__ A, const __half* __restrict__ B,
    __half* __restrict__ C, int lda, int Cstr, int nk)
{
    extern __shared__ __half smem[];
    int t = threadIdx.x;
    int lane = t & 31;
    int w = t >> 5;
    int wm = (w >> 2) * 64;
    int wn = (w & 3) * 32;
    int bm = blockIdx.y * 128;
    int bn = blockIdx.x * 128;

    float acc[4][4][4];
    #pragma unroll
    for (int i = 0; i < 4; i++)
        #pragma unroll
        for (int j = 0; j < 4; j++)
            #pragma unroll
            for (int x = 0; x < 4; x++) acc[i][j][x] = 0.f;

    auto load_stage = [&](int kt, int s) {
        __half* st = smem + s * STAGE_ELEMS;
        #pragma unroll
        for (int i = 0; i < 4; i++) {
            int q = t + i * 256;
            int r = q >> 3, ch = q & 7;
            const __half* src = A + (size_t)(bm + r) * lda + kt * BK + ch * 8;
            CP16(sm_u32(st + SA_OFF + r * 64 + ((ch ^ (r & 7)) << 3)), src);
        }
        #pragma unroll
        for (int i = 0; i < 4; i++) {
            int q = t + i * 256;
            int kr = q >> 4, c = q & 15;
            size_t goff = (size_t)(kt * BK + kr) * Cstr + bn + c * 8;
            CP16(sm_u32(st + SB_OFF + kr * 128 + ((c ^ (kr & 7)) << 3)), B + goff);
        }
    };

    // per-ks fragment load into caller-provided buffers
    auto load_frags = [&](__half* st, int ks, unsigned (&ah)[4][4], unsigned (&bf)[2][4]) {
        int kc = ks * 2 + (lane >> 4);
        #pragma unroll
        for (int mi = 0; mi < 4; mi++) {
            int r = wm + mi * 16 + (lane & 15);
            LDMX4(ah[mi], sm_u32(st + SA_OFF + r * 64 + ((kc ^ (r & 7)) << 3)));
        }
        int kb = ks * 16 + (lane & 15);
        #pragma unroll
        for (int nq = 0; nq < 2; nq++) {
            int n = wn + nq * 16 + (lane >> 4) * 8;
            int c = n >> 3;
            LDMX4T(bf[nq], sm_u32(st + SB_OFF + kb * 128 + ((c ^ (kb & 7)) << 3)));
        }
    };
    auto mma_all = [&](unsigned (&ah)[4][4], unsigned (&bf)[2][4]) {
        #pragma unroll
        for (int mi = 0; mi < 4; mi++)
            #pragma unroll
            for (int j = 0; j < 4; j++)
                MMAF16(acc[mi][j], ah[mi], (&bf[j >> 1][(j & 1) * 2]));
    };

    #pragma unroll
    for (int s = 0; s < 2; s++) {
        if (s < nk) load_stage(s, s);
        asm volatile("cp.async.commit_group;");
    }

    unsigned ahA[4][4], bfA[2][4], ahB[4][4], bfB[2][4];

    for (int kt = 0; kt < nk; kt++) {
        if (kt + 1 < nk) asm volatile("cp.async.wait_group 1;");
        else             asm volatile("cp.async.wait_group 0;");
        __syncthreads();
        if (kt + 2 < nk) {
            load_stage(kt + 2, (kt + 2) % 3);
            asm volatile("cp.async.commit_group;");
        }

        __half* st = smem + (kt % 3) * STAGE_ELEMS;
        // software-pipelined ks: LDSM for ks+1 issued before MMAs of ks
        load_frags(st, 0, ahA, bfA);
        load_frags(st, 1, ahB, bfB);
        mma_all(ahA, bfA);
        load_frags(st, 2, ahA, bfA);
        mma_all(ahB, bfB);
        load_frags(st, 3, ahB, bfB);
        mma_all(ahA, bfA);
        mma_all(ahB, bfB);
        __syncthreads();
    }

    #pragma unroll
    for (int mi = 0; mi < 4; mi++)
        #pragma unroll
        for (int j = 0; j < 4; j++) {
            int row = bm + wm + mi * 16 + (lane >> 2);
            int col = bn + wn + j * 8 + (lane & 3) * 2;
            *(__half2*)(C + (size_t)row * Cstr + col) =
                __floats2half2_rn(acc[mi][j][0], acc[mi][j][1]);
            *(__half2*)(C + (size_t)(row + 8) * Cstr + col) =
                __floats2half2_rn(acc[mi][j][2], acc[mi][j][3]);
        }
}

// ---------------- attention coefficients (fp16 h) ----------------
__global__ void k_alpha(const float* __restrict__ asW,
                        const float* __restrict__ adW, int H, int hstr) {
    int n = blockIdx.x;
    int h = threadIdx.x >> 5;
    int lane = threadIdx.x & 31;
    if (h >= H) return;
    const __half2* hrow = (const __half2*)(g_h + (size_t)n * hstr + h * CC);
    const float* pa = asW + h * CC;
    const float* pd = adW + h * CC;
    float s1 = 0.f, s2 = 0.f;
    for (int c2 = lane; c2 < CC / 2; c2 += 32) {
        float2 v = __half22float2(hrow[c2]);
        s1 += v.x * pa[2 * c2] + v.y * pa[2 * c2 + 1];
        s2 += v.x * pd[2 * c2] + v.y * pd[2 * c2 + 1];
    }
    #pragma unroll
    for (int o = 16; o; o >>= 1) {
        s1 += __shfl_xor_sync(0xffffffffu, s1, o);
        s2 += __shfl_xor_sync(0xffffffffu, s2, o);
    }
    if (lane == 0) {
        g_asrc[n * HMAX + h] = s1;
        g_adst[n * HMAX + h] = s2;
    }
}

// ---------------- fused softmax + aggregation, warp-per-head ----------------
__device__ __forceinline__ float gelu_exact(float v) {
    return 0.5f * v * (1.0f + erff(v * 0.70710678118654752f));
}

__device__ __forceinline__ void acc8(float* acc, float a, const float4& f) {
    const __half2* p = (const __half2*)&f;
    #pragma unroll
    for (int q = 0; q < 4; q++) {
        float2 v = __half22float2(p[q]);
        acc[2 * q]     += a * v.x;
        acc[2 * q + 1] += a * v.y;
    }
}

__global__ void k_smagg(const float* __restrict__ bias, int H, int hstr,
                        __half* __restrict__ outH, float* __restrict__ outF,
                        float* __restrict__ attn_out) {
    int d = blockIdx.x;
    int h = threadIdx.x >> 5;
    int lane = threadIdx.x & 31;
    if (h >= H) return;
    int beg = g_off[d], end = g_off[d + 1];
    int deg = end - beg;
    float ad = g_adst[d * HMAX + h];

    int cbase = lane * 8;
    bool act = cbase < CC;
    float acc[8];
    #pragma unroll
    for (int q = 0; q < 8; q++) acc[q] = 0.f;
    const __half* hb = g_h + h * CC + cbase;
    float inv;

    if (deg <= 32) {
        int k = beg + lane;
        bool has = k < end;
        int src = has ? g_srcCSR[k] : 0;
        float v = has ? (g_asrc[src * HMAX + h] + ad) : -INFINITY;
        v = v > 0.f ? v : 0.2f * v;
        float mx = v;
        #pragma unroll
        for (int o = 16; o; o >>= 1) mx = fmaxf(mx, __shfl_xor_sync(0xffffffffu, mx, o));
        float ex = has ? expf(v - mx) : 0.f;
        float sum = ex;
        #pragma unroll
        for (int o = 16; o; o >>= 1) sum += __shfl_xor_sync(0xffffffffu, sum, o);
        inv = 1.f / sum;

        if (attn_out && h == 0 && has)
            attn_out[g_eidx[k]] = ex * inv;

        int i = 0;
        for (; i + 4 <= deg; i += 4) {
            int s0 = __shfl_sync(0xffffffffu, src, i);
            int s1 = __shfl_sync(0xffffffffu, src, i + 1);
            int s2 = __shfl_sync(0xffffffffu, src, i + 2);
            int s3 = __shfl_sync(0xffffffffu, src, i + 3);
            float a0 = __shfl_sync(0xffffffffu, ex, i);
            float a1 = __shfl_sync(0xffffffffu, ex, i + 1);
            float a2 = __shfl_sync(0xffffffffu, ex, i + 2);
            float a3 = __shfl_sync(0xffffffffu, ex, i + 3);
            if (act) {
                float4 f0 = *(const float4*)(hb + (size_t)s0 * hstr);
                float4 f1 = *(const float4*)(hb + (size_t)s1 * hstr);
                float4 f2 = *(const float4*)(hb + (size_t)s2 * hstr);
                float4 f3 = *(const float4*)(hb + (size_t)s3 * hstr);
                acc8(acc, a0, f0);
                acc8(acc, a1, f1);
                acc8(acc, a2, f2);
                acc8(acc, a3, f3);
            }
        }
        for (; i < deg; i++) {
            int s = __shfl_sync(0xffffffffu, src, i);
            float a = __shfl_sync(0xffffffffu, ex, i);
            if (act) {
                float4 f = *(const float4*)(hb + (size_t)s * hstr);
                acc8(acc, a, f);
            }
        }
    } else {
        float mx = -INFINITY;
        for (int k = beg + lane; k < end; k += 32) {
            float v = g_asrc[g_srcCSR[k] * HMAX + h] + ad;
            v = v > 0.f ? v : 0.2f * v;
            g_alphaCSR[k * HMAX + h] = v;
            mx = fmaxf(mx, v);
        }
        #pragma unroll
        for (int o = 16; o; o >>= 1) mx = fmaxf(mx, __shfl_xor_sync(0xffffffffu, mx, o));
        float sum = 0.f;
        for (int k = beg + lane; k < end; k += 32) {
            float ex = expf(g_alphaCSR[k * HMAX + h] - mx);
            g_alphaCSR[k * HMAX + h] = ex;
            sum += ex;
        }
        #pragma unroll
        for (int o = 16; o; o >>= 1) sum += __shfl_xor_sync(0xffffffffu, sum, o);
        inv = 1.f / sum;

        if (attn_out && h == 0) {
            for (int k = beg + lane; k < end; k += 32)
                attn_out[g_eidx[k]] = g_alphaCSR[k * HMAX] * inv;
        }

        int k = beg;
        for (; k + 4 <= end; k += 4) {
            int s0 = g_srcCSR[k],     s1 = g_srcCSR[k + 1];
            int s2 = g_srcCSR[k + 2], s3 = g_srcCSR[k + 3];
            float a0 = g_alphaCSR[k * HMAX + h];
            float a1 = g_alphaCSR[(k + 1) * HMAX + h];
            float a2 = g_alphaCSR[(k + 2) * HMAX + h];
            float a3 = g_alphaCSR[(k + 3) * HMAX + h];
            if (act) {
                float4 f0 = *(const float4*)(hb + (size_t)s0 * hstr);
                float4 f1 = *(const float4*)(hb + (size_t)s1 * hstr);
                float4 f2 = *(const float4*)(hb + (size_t)s2 * hstr);
                float4 f3 = *(const float4*)(hb + (size_t)s3 * hstr);
                acc8(acc, a0, f0);
                acc8(acc, a1, f1);
                acc8(acc, a2, f2);
                acc8(acc, a3, f3);
            }
        }
        for (; k < end; k++) {
            int s = g_srcCSR[k];
            float a = g_alphaCSR[k * HMAX + h];
            if (act) {
                float4 f = *(const float4*)(hb + (size_t)s * hstr);
                acc8(acc, a, f);
            }
        }
    }

    if (!act) return;
    float o[8];
    #pragma unroll
    for (int q = 0; q < 8; q++)
        o[q] = gelu_exact(acc[q] * inv + bias[h * CC + cbase + q]);

    if (outF) {
        float* dst = outF + (size_t)d * (H * CC) + h * CC + cbase;
        *(float4*)dst       = make_float4(o[0], o[1], o[2], o[3]);
        *(float4*)(dst + 4) = make_float4(o[4], o[5], o[6], o[7]);
    } else {
        __half2 hp[4];
        #pragma unroll
        for (int q = 0; q < 4; q++)
            hp[q] = __floats2half2_rn(o[2 * q], o[2 * q + 1]);
        *(float4*)(outH + (size_t)d * KA + h * CC + cbase) = *(float4*)hp;
    }
}

// ---------------- host launch ----------------
extern "C" void kernel_launch(void* const* d_in, const int* in_sizes, int n_in,
                              void* d_out, int out_size) {
    const float* X  = (const float*)d_in[0];
    const int*   EI = (const int*)d_in[1];
    const float *W[5], *AS[5], *AD[5], *B[5];
    int idx = 2;
    for (int i = 0; i < 5; i++) {
        W[i]  = (const float*)d_in[idx++];
        AS[i] = (const float*)d_in[idx++];
        AD[i] = (const float*)d_in[idx++];
        B[i]  = (const float*)d_in[idx++];
    }
    float* out = (float*)d_out;

    __half *Ah, *Wh, *hbuf;
    cudaGetSymbolAddress((void**)&Ah, g_Ah);
    cudaGetSymbolAddress((void**)&Wh, g_Wh);
    cudaGetSymbolAddress((void**)&hbuf, g_h);

    const int SMEM_DYN = 3 * STAGE_ELEMS * 2;   // 96 KB
    cudaFuncSetAttribute(k_gemm_mma, cudaFuncAttributeMaxDynamicSharedMemorySize, SMEM_DYN);

    const int KP [5] = {256, 832, 832, 832, 832};
    const int NP [5] = {896, 896, 896, 896, 256};
    const int HD [5] = {4, 4, 4, 4, 1};

    k_init_A<<<(NPAD * KA + 255) / 256, 256>>>(X);                             // 0
    k_convert_W_all<<<(5 * WSZ + 255) / 256, 256>>>(W[0], W[1], W[2], W[3], W[4]); // 1
    k_zero_deg<<<(NN + 255) / 256, 256>>>();                                   // 2

    for (int i = 0; i < 5; i++) {
        int Kp = KP[i], Np = NP[i], H = HD[i];
        dim3 grid(Np / 128, NPAD / 128);
        k_gemm_mma<<<grid, 256, SMEM_DYN>>>(Ah, Wh + (size_t)i * WSZ, hbuf,
                                            KA, Np, Kp / BK);  // i==0 -> slot 3
        if (i == 0) {
            k_build_edges<<<(E2 + 255) / 256, 256>>>(EI);
            k_scan<<<1, 1024>>>();
            k_scatter<<<(E2 + 255) / 256, 256>>>();
        }
        k_alpha<<<NN, 32 * H>>>(AS[i], AD[i], H, Np);
        if (i < 4) {
            k_smagg<<<NN, 32 * H>>>(B[i], H, Np, Ah, nullptr, nullptr);
        } else {
            k_smagg<<<NN, 32 * H>>>(B[i], H, Np, nullptr, out, out + (size_t)NN * 200);
        }
    }
}

// round 15
// speedup vs baseline: 1.0320x; 1.0320x over previous
#include <cuda_runtime.h>
#include <cuda_fp16.h>
#include <math.h>

#define NN 10000
#define NPAD 10112          // 79 * 128
#define EE 100000
#define E2 110000
#define HMAX 4
#define CC 200
#define KA 832              // A col stride; layer0 uses cols 0..255
#define WSZ (832 * 896)     // per-layer converted W size

// ---------------- scratch (device globals; no allocs allowed) ----------------
__device__ __half g_Ah[NPAD * KA];        // fp16 activations
__device__ __half g_Wh[5 * WSZ];          // fp16 weights, [layer][Kp][Np]
__device__ __half g_h[NPAD * 896];        // GEMM output h (fp16, padded stride)
__device__ float g_asrc[NN * HMAX];
__device__ float g_adst[NN * HMAX];
__device__ float g_alphaCSR[E2 * HMAX];
__device__ int   g_srcCSR[E2];
__device__ int   g_eidx[E2];
__device__ int   g_srcv[E2];
__device__ int   g_dstv[E2];
__device__ int   g_deg[NN];
__device__ int   g_off[NN + 1];
__device__ int   g_pos[NN];

// ---------------- CSR construction ----------------
__global__ void k_zero_deg() {
    int i = blockIdx.x * blockDim.x + threadIdx.x;
    if (i < NN) g_deg[i] = 0;
}

__global__ void k_build_edges(const int* __restrict__ ei) {
    int e = blockIdx.x * blockDim.x + threadIdx.x;
    if (e >= E2) return;
    int s, d;
    if (e < EE) { s = ei[e]; d = ei[EE + e]; }
    else        { s = d = e - EE; }
    g_srcv[e] = s;
    g_dstv[e] = d;
    atomicAdd(&g_deg[d], 1);
}

__global__ void k_scan() {
    __shared__ int ssum[1024];
    const int CH = (NN + 1023) / 1024;
    int t = threadIdx.x;
    int start = t * CH;
    int local = 0;
    for (int i = 0; i < CH; i++) {
        int idx = start + i;
        if (idx < NN) local += g_deg[idx];
    }
    ssum[t] = local;
    __syncthreads();
    for (int d = 1; d < 1024; d <<= 1) {
        int v = (t >= d) ? ssum[t - d] : 0;
        __syncthreads();
        ssum[t] += v;
        __syncthreads();
    }
    int run = (t == 0) ? 0 : ssum[t - 1];
    for (int i = 0; i < CH; i++) {
        int idx = start + i;
        if (idx < NN) {
            g_off[idx] = run;
            g_pos[idx] = run;
            run += g_deg[idx];
        }
    }
    if (t == 1023) g_off[NN] = ssum[1023];
}

__global__ void k_scatter() {
    int e = blockIdx.x * blockDim.x + threadIdx.x;
    if (e >= E2) return;
    int p = atomicAdd(&g_pos[g_dstv[e]], 1);
    g_eidx[p] = e;
    g_srcCSR[p] = g_srcv[e];
}

// ---------------- conversions ----------------
__global__ void k_init_A(const float* __restrict__ X) {
    int idx = blockIdx.x * blockDim.x + threadIdx.x;
    if (idx >= NPAD * KA) return;
    int r = idx / KA, c = idx % KA;
    float v = (r < NN && c < 200) ? X[r * 200 + c] : 0.f;
    g_Ah[idx] = __float2half(v);
}

__global__ void k_convert_W_all(const float* W0, const float* W1, const float* W2,
                                const float* W3, const float* W4) {
    int idx = blockIdx.x * blockDim.x + threadIdx.x;
    if (idx >= 5 * WSZ) return;
    int layer = idx / WSZ;
    int q = idx % WSZ;
    int Np = (layer == 4) ? 256 : 896;
    int Nc = (layer == 4) ? 200 : 800;
    int K  = (layer == 0) ? 200 : 800;
    if (q >= 832 * Np) return;
    int r = q / Np, c = q % Np;
    const float* W = (layer == 0) ? W0 : (layer == 1) ? W1 : (layer == 2) ? W2
                     : (layer == 3) ? W3 : W4;
    float v = (r < K && c < Nc) ? W[r * Nc + c] : 0.f;
    g_Wh[(size_t)layer * WSZ + q] = __float2half(v);
}

// ---------------- fp16 mma.sync GEMM: 1 sync/tile + peeled K tail ----------
#define BK 64
#define STAGE_ELEMS 16384
#define SA_OFF 0
#define SB_OFF 8192

__device__ __forceinline__ unsigned sm_u32(const void* p) {
    return (unsigned)__cvta_generic_to_shared(p);
}

#define CP16(dst, src) \
    asm volatile("cp.async.cg.shared.global [%0], [%1], 16;" :: "r"(dst), "l"(src))
#define LDMX4(r, addr) \
    asm volatile("ldmatrix.sync.aligned.m8n8.x4.shared.b16 {%0,%1,%2,%3}, [%4];" \
        : "=r"((r)[0]), "=r"((r)[1]), "=r"((r)[2]), "=r"((r)[3]) : "r"(addr))
#define LDMX4T(r, addr) \
    asm volatile("ldmatrix.sync.aligned.m8n8.x4.trans.shared.b16 {%0,%1,%2,%3}, [%4];" \
        : "=r"((r)[0]), "=r"((r)[1]), "=r"((r)[2]), "=r"((r)[3]) : "r"(addr))
#define MMAF16(d, a, b) \
    asm volatile("mma.sync.aligned.m16n8k16.row.col.f32.f16.f16.f32 " \
        "{%0,%1,%2,%3}, {%4,%5,%6,%7}, {%8,%9}, {%0,%1,%2,%3};" \
        : "+f"((d)[0]), "+f"((d)[1]), "+f"((d)[2]), "+f"((d)[3]) \
        : "r"((a)[0]), "r"((a)[1]), "r"((a)[2]), "r"((a)[3]), "r"((b)[0]), "r"((b)[1]))

__global__ __launch_bounds__(256, 2) void k_gemm_mma(
    const __half* __restrict__ A, const __half* __restrict__ B,
    __half* __restrict__ C, int lda, int Cstr, int nt, int kstail)
{
    extern __shared__ __half smem[];
    int t = threadIdx.x;
    int lane = t & 31;
    int w = t >> 5;
    int wm = (w >> 2) * 64;
    int wn = (w & 3) * 32;
    int bm = blockIdx.y * 128;
    int bn = blockIdx.x * 128;

    float acc[4][4][4];
    #pragma unroll
    for (int i = 0; i < 4; i++)
        #pragma unroll
        for (int j = 0; j < 4; j++)
            #pragma unroll
            for (int x = 0; x < 4; x++) acc[i][j][x] = 0.f;

    auto load_stage = [&](int kt, int s) {
        __half* st = smem + s * STAGE_ELEMS;
        #pragma unroll
        for (int i = 0; i < 4; i++) {
            int q = t + i * 256;
            int r = q >> 3, ch = q & 7;
            const __half* src = A + (size_t)(bm + r) * lda + kt * BK + ch * 8;
            CP16(sm_u32(st + SA_OFF + r * 64 + ((ch ^ (r & 7)) << 3)), src);
        }
        #pragma unroll
        for (int i = 0; i < 4; i++) {
            int q = t + i * 256;
            int kr = q >> 4, c = q & 15;
            size_t goff = (size_t)(kt * BK + kr) * Cstr + bn + c * 8;
            CP16(sm_u32(st + SB_OFF + kr * 128 + ((c ^ (kr & 7)) << 3)), B + goff);
        }
    };

    auto body = [&](__half* st, int ks) {
        unsigned ah[4][4];
        int kc = ks * 2 + (lane >> 4);
        #pragma unroll
        for (int mi = 0; mi < 4; mi++) {
            int r = wm + mi * 16 + (lane & 15);
            LDMX4(ah[mi], sm_u32(st + SA_OFF + r * 64 + ((kc ^ (r & 7)) << 3)));
        }
        unsigned bf[2][4];
        int kb = ks * 16 + (lane & 15);
        #pragma unroll
        for (int nq = 0; nq < 2; nq++) {
            int n = wn + nq * 16 + (lane >> 4) * 8;
            int c = n >> 3;
            LDMX4T(bf[nq], sm_u32(st + SB_OFF + kb * 128 + ((c ^ (kb & 7)) << 3)));
        }
        #pragma unroll
        for (int mi = 0; mi < 4; mi++)
            #pragma unroll
            for (int j = 0; j < 4; j++)
                MMAF16(acc[mi][j], ah[mi], (&bf[j >> 1][(j & 1) * 2]));
    };

    #pragma unroll
    for (int s = 0; s < 2; s++) {
        if (s < nt) load_stage(s, s);
        asm volatile("cp.async.commit_group;");
    }

    for (int kt = 0; kt < nt; kt++) {
        if (kt + 1 < nt) asm volatile("cp.async.wait_group 1;");
        else             asm volatile("cp.async.wait_group 0;");
        __syncthreads();                       // single barrier per tile
        if (kt + 2 < nt) {
            load_stage(kt + 2, (kt + 2) % 3);
            asm volatile("cp.async.commit_group;");
        }

        __half* st = smem + (kt % 3) * STAGE_ELEMS;
        if (kt + 1 < nt) {                     // full tile: 4 ks-steps
            #pragma unroll
            for (int ks = 0; ks < 4; ks++) body(st, ks);
        } else {                               // peeled tail: kstail steps
            body(st, 0);
            if (kstail > 1) body(st, 1);
        }
    }

    #pragma unroll
    for (int mi = 0; mi < 4; mi++)
        #pragma unroll
        for (int j = 0; j < 4; j++) {
            int row = bm + wm + mi * 16 + (lane >> 2);
            int col = bn + wn + j * 8 + (lane & 3) * 2;
            *(__half2*)(C + (size_t)row * Cstr + col) =
                __floats2half2_rn(acc[mi][j][0], acc[mi][j][1]);
            *(__half2*)(C + (size_t)(row + 8) * Cstr + col) =
                __floats2half2_rn(acc[mi][j][2], acc[mi][j][3]);
        }
}

// ---------------- attention coefficients (fp16 h) ----------------
__global__ void k_alpha(const float* __restrict__ asW,
                        const float* __restrict__ adW, int H, int hstr) {
    int n = blockIdx.x;
    int h = threadIdx.x >> 5;
    int lane = threadIdx.x & 31;
    if (h >= H) return;
    const __half2* hrow = (const __half2*)(g_h + (size_t)n * hstr + h * CC);
    const float* pa = asW + h * CC;
    const float* pd = adW + h * CC;
    float s1 = 0.f, s2 = 0.f;
    for (int c2 = lane; c2 < CC / 2; c2 += 32) {
        float2 v = __half22float2(hrow[c2]);
        s1 += v.x * pa[2 * c2] + v.y * pa[2 * c2 + 1];
        s2 += v.x * pd[2 * c2] + v.y * pd[2 * c2 + 1];
    }
    #pragma unroll
    for (int o = 16; o; o >>= 1) {
        s1 += __shfl_xor_sync(0xffffffffu, s1, o);
        s2 += __shfl_xor_sync(0xffffffffu, s2, o);
    }
    if (lane == 0) {
        g_asrc[n * HMAX + h] = s1;
        g_adst[n * HMAX + h] = s2;
    }
}

// ---------------- fused softmax + aggregation, warp-per-head ----------------
__device__ __forceinline__ float gelu_exact(float v) {
    return 0.5f * v * (1.0f + erff(v * 0.70710678118654752f));
}

__device__ __forceinline__ void acc8(float* acc, float a, const float4& f) {
    const __half2* p = (const __half2*)&f;
    #pragma unroll
    for (int q = 0; q < 4; q++) {
        float2 v = __half22float2(p[q]);
        acc[2 * q]     += a * v.x;
        acc[2 * q + 1] += a * v.y;
    }
}

__global__ void k_smagg(const float* __restrict__ bias, int H, int hstr,
                        __half* __restrict__ outH, float* __restrict__ outF,
                        float* __restrict__ attn_out) {
    int d = blockIdx.x;
    int h = threadIdx.x >> 5;
    int lane = threadIdx.x & 31;
    if (h >= H) return;
    int beg = g_off[d], end = g_off[d + 1];
    int deg = end - beg;
    float ad = g_adst[d * HMAX + h];

    int cbase = lane * 8;
    bool act = cbase < CC;
    float acc[8];
    #pragma unroll
    for (int q = 0; q < 8; q++) acc[q] = 0.f;
    const __half* hb = g_h + h * CC + cbase;
    float inv;

    if (deg <= 32) {
        int k = beg + lane;
        bool has = k < end;
        int src = has ? g_srcCSR[k] : 0;
        float v = has ? (g_asrc[src * HMAX + h] + ad) : -INFINITY;
        v = v > 0.f ? v : 0.2f * v;
        float mx = v;
        #pragma unroll
        for (int o = 16; o; o >>= 1) mx = fmaxf(mx, __shfl_xor_sync(0xffffffffu, mx, o));
        float ex = has ? expf(v - mx) : 0.f;
        float sum = ex;
        #pragma unroll
        for (int o = 16; o; o >>= 1) sum += __shfl_xor_sync(0xffffffffu, sum, o);
        inv = 1.f / sum;

        if (attn_out && h == 0 && has)
            attn_out[g_eidx[k]] = ex * inv;

        int i = 0;
        for (; i + 4 <= deg; i += 4) {
            int s0 = __shfl_sync(0xffffffffu, src, i);
            int s1 = __shfl_sync(0xffffffffu, src, i + 1);
            int s2 = __shfl_sync(0xffffffffu, src, i + 2);
            int s3 = __shfl_sync(0xffffffffu, src, i + 3);
            float a0 = __shfl_sync(0xffffffffu, ex, i);
            float a1 = __shfl_sync(0xffffffffu, ex, i + 1);
            float a2 = __shfl_sync(0xffffffffu, ex, i + 2);
            float a3 = __shfl_sync(0xffffffffu, ex, i + 3);
            if (act) {
                float4 f0 = *(const float4*)(hb + (size_t)s0 * hstr);
                float4 f1 = *(const float4*)(hb + (size_t)s1 * hstr);
                float4 f2 = *(const float4*)(hb + (size_t)s2 * hstr);
                float4 f3 = *(const float4*)(hb + (size_t)s3 * hstr);
                acc8(acc, a0, f0);
                acc8(acc, a1, f1);
                acc8(acc, a2, f2);
                acc8(acc, a3, f3);
            }
        }
        for (; i < deg; i++) {
            int s = __shfl_sync(0xffffffffu, src, i);
            float a = __shfl_sync(0xffffffffu, ex, i);
            if (act) {
                float4 f = *(const float4*)(hb + (size_t)s * hstr);
                acc8(acc, a, f);
            }
        }
    } else {
        float mx = -INFINITY;
        for (int k = beg + lane; k < end; k += 32) {
            float v = g_asrc[g_srcCSR[k] * HMAX + h] + ad;
            v = v > 0.f ? v : 0.2f * v;
            g_alphaCSR[k * HMAX + h] = v;
            mx = fmaxf(mx, v);
        }
        #pragma unroll
        for (int o = 16; o; o >>= 1) mx = fmaxf(mx, __shfl_xor_sync(0xffffffffu, mx, o));
        float sum = 0.f;
        for (int k = beg + lane; k < end; k += 32) {
            float ex = expf(g_alphaCSR[k * HMAX + h] - mx);
            g_alphaCSR[k * HMAX + h] = ex;
            sum += ex;
        }
        #pragma unroll
        for (int o = 16; o; o >>= 1) sum += __shfl_xor_sync(0xffffffffu, sum, o);
        inv = 1.f / sum;

        if (attn_out && h == 0) {
            for (int k = beg + lane; k < end; k += 32)
                attn_out[g_eidx[k]] = g_alphaCSR[k * HMAX] * inv;
        }

        int k = beg;
        for (; k + 4 <= end; k += 4) {
            int s0 = g_srcCSR[k],     s1 = g_srcCSR[k + 1];
            int s2 = g_srcCSR[k + 2], s3 = g_srcCSR[k + 3];
            float a0 = g_alphaCSR[k * HMAX + h];
            float a1 = g_alphaCSR[(k + 1) * HMAX + h];
            float a2 = g_alphaCSR[(k + 2) * HMAX + h];
            float a3 = g_alphaCSR[(k + 3) * HMAX + h];
            if (act) {
                float4 f0 = *(const float4*)(hb + (size_t)s0 * hstr);
                float4 f1 = *(const float4*)(hb + (size_t)s1 * hstr);
                float4 f2 = *(const float4*)(hb + (size_t)s2 * hstr);
                float4 f3 = *(const float4*)(hb + (size_t)s3 * hstr);
                acc8(acc, a0, f0);
                acc8(acc, a1, f1);
                acc8(acc, a2, f2);
                acc8(acc, a3, f3);
            }
        }
        for (; k < end; k++) {
            int s = g_srcCSR[k];
            float a = g_alphaCSR[k * HMAX + h];
            if (act) {
                float4 f = *(const float4*)(hb + (size_t)s * hstr);
                acc8(acc, a, f);
            }
        }
    }

    if (!act) return;
    float o[8];
    #pragma unroll
    for (int q = 0; q < 8; q++)
        o[q] = gelu_exact(acc[q] * inv + bias[h * CC + cbase + q]);

    if (outF) {
        float* dst = outF + (size_t)d * (H * CC) + h * CC + cbase;
        *(float4*)dst       = make_float4(o[0], o[1], o[2], o[3]);
        *(float4*)(dst + 4) = make_float4(o[4], o[5], o[6], o[7]);
    } else {
        __half2 hp[4];
        #pragma unroll
        for (int q = 0; q < 4; q++)
            hp[q] = __floats2half2_rn(o[2 * q], o[2 * q + 1]);
        *(float4*)(outH + (size_t)d * KA + h * CC + cbase) = *(float4*)hp;
    }
}

// ---------------- host launch ----------------
extern "C" void kernel_launch(void* const* d_in, const int* in_sizes, int n_in,
                              void* d_out, int out_size) {
    const float* X  = (const float*)d_in[0];
    const int*   EI = (const int*)d_in[1];
    const float *W[5], *AS[5], *AD[5], *B[5];
    int idx = 2;
    for (int i = 0; i < 5; i++) {
        W[i]  = (const float*)d_in[idx++];
        AS[i] = (const float*)d_in[idx++];
        AD[i] = (const float*)d_in[idx++];
        B[i]  = (const float*)d_in[idx++];
    }
    float* out = (float*)d_out;

    __half *Ah, *Wh, *hbuf;
    cudaGetSymbolAddress((void**)&Ah, g_Ah);
    cudaGetSymbolAddress((void**)&Wh, g_Wh);
    cudaGetSymbolAddress((void**)&hbuf, g_h);

    const int SMEM_DYN = 3 * STAGE_ELEMS * 2;   // 96 KB
    cudaFuncSetAttribute(k_gemm_mma, cudaFuncAttributeMaxDynamicSharedMemorySize, SMEM_DYN);

    const int NT [5] = {4, 13, 13, 13, 13};    // k-tiles (last is partial)
    const int KT [5] = {1, 2, 2, 2, 2};        // ks-steps in last tile
    const int NP [5] = {896, 896, 896, 896, 256};
    const int HD [5] = {4, 4, 4, 4, 1};

    k_init_A<<<(NPAD * KA + 255) / 256, 256>>>(X);                             // 0
    k_convert_W_all<<<(5 * WSZ + 255) / 256, 256>>>(W[0], W[1], W[2], W[3], W[4]); // 1
    k_zero_deg<<<(NN + 255) / 256, 256>>>();                                   // 2

    for (int i = 0; i < 5; i++) {
        int Np = NP[i], H = HD[i];
        dim3 grid(Np / 128, NPAD / 128);
        k_gemm_mma<<<grid, 256, SMEM_DYN>>>(Ah, Wh + (size_t)i * WSZ, hbuf,
                                            KA, Np, NT[i], KT[i]);  // i==0 -> slot 3
        if (i == 0) {
            k_build_edges<<<(E2 + 255) / 256, 256>>>(EI);
            k_scan<<<1, 1024>>>();
            k_scatter<<<(E2 + 255) / 256, 256>>>();
        }
        k_alpha<<<NN, 32 * H>>>(AS[i], AD[i], H, Np);
        if (i < 4) {
            k_smagg<<<NN, 32 * H>>>(B[i], H, Np, Ah, nullptr, nullptr);
        } else {
            k_smagg<<<NN, 32 * H>>>(B[i], H, Np, nullptr, out, out + (size_t)NN * 200);
        }
    }
}